// round 4
// baseline (speedup 1.0000x reference)
#include <cuda_runtime.h>
#include <cstdint>

// Problem constants
#define BS_    64
#define SEQ_   1024
#define D_     800
#define NSLOT_ 64
#define NLAB_  72
#define NPOOL_ (BS_ * NSLOT_)   // 4096
#define D4_    (D_ / 4)         // 200

// Scratch for pooled vectors (allocation-free rule: __device__ global)
__device__ float g_pool[NPOOL_ * D_];

// ---------------------------------------------------------------------------
// f32x2 packed-math helpers (sm_100+)
// ---------------------------------------------------------------------------
typedef unsigned long long ull;
__device__ __forceinline__ ull splat2(float x) {
    ull r; asm("mov.b64 %0, {%1, %1};" : "=l"(r) : "f"(x)); return r;
}
__device__ __forceinline__ void fma2(ull& d, ull a, ull b) {
    asm("fma.rn.f32x2 %0, %1, %2, %0;" : "+l"(d) : "l"(a), "l"(b));
}
__device__ __forceinline__ void unpack2(ull v, float& lo, float& hi) {
    asm("mov.b64 {%0, %1}, %2;" : "=f"(lo), "=f"(hi) : "l"(v));
}

// ---------------------------------------------------------------------------
// Kernel 1: ragged span mean pooling (near DRAM floor).
// ---------------------------------------------------------------------------
__global__ __launch_bounds__(256) void pool_kernel(
    const float* __restrict__ hs,
    const int*   __restrict__ begins,
    const int*   __restrict__ lens)
{
    const int slot = blockIdx.x;
    const int b    = slot >> 6;
    const int begin = begins[slot];
    const int len   = lens[slot];
    const float inv = 1.0f / (float)(len + 1);

    const int t = threadIdx.x;
    if (t >= D4_) return;

    const float4* __restrict__ row =
        reinterpret_cast<const float4*>(hs) + (size_t)(b * SEQ_ + begin) * D4_;

    float4 acc = row[t];
    #pragma unroll 7
    for (int r = 1; r <= len; ++r) {
        float4 v = row[(size_t)r * D4_ + t];
        acc.x += v.x; acc.y += v.y; acc.z += v.z; acc.w += v.w;
    }
    acc.x *= inv; acc.y *= inv; acc.z *= inv; acc.w *= inv;
    reinterpret_cast<float4*>(g_pool)[(size_t)slot * D4_ + t] = acc;
}

// ---------------------------------------------------------------------------
// Kernel 2: logits = pool (4096 x 800) @ W (800 x 72) + bias, fp32.
//
// 256 threads = 8 warps; warp w owns K-range [100w, 100w+100) over the SAME
// 32x72 tile (no block barriers in the mainloop). Shared A-tile As[k][34]
// (k-major) holds the whole 32x800 block slice. Per-warp private B chunks
// (2 x 50k x 72). Thread tile 8m x 9n:
//   cols tn*8..tn*8+7 : B n-pairs as ULL (LDS.64), A splatted -> 32 FFMA2
//   col  64+tn        : A m-pairs (LDS.64), B splatted        ->  4 FFMA2
// acc = 40 ULL = 80 regs; fill loops modest-unrolled to avoid spills.
// ---------------------------------------------------------------------------
#define BM_      32
#define KSLICE_  100
#define BKC_     50
#define ASTR_    34                       // even -> 8B-aligned m-pair LDS.64
#define AS_FLOATS_   (D_ * ASTR_)         // 27200
#define BW_FLOATS_   (BKC_ * NLAB_)       // 3600 per warp chunk
#define SMEM_FLOATS_ (AS_FLOATS_ + 8 * BW_FLOATS_)   // 56000
#define SMEM_BYTES_  (SMEM_FLOATS_ * 4)              // 224000 B
#define RED_FLOATS_  (BM_ * NLAB_)        // 2304 per slice (reuses As region)

__global__ __launch_bounds__(256, 1) void gemm_kernel(
    const float* __restrict__ W,     // (800, 72) row-major
    const float* __restrict__ bias,  // (72,)
    float*       __restrict__ out)   // (4096, 72) row-major
{
    extern __shared__ float smem[];
    float* As = smem;                         // [800][34] k-major
    float* Bw = smem + AS_FLOATS_ + (threadIdx.x >> 5) * BW_FLOATS_;

    const int tid   = threadIdx.x;
    const int wrp   = tid >> 5;               // 0..7 (K-slice)
    const int lane  = tid & 31;
    const int tm    = lane >> 3;              // 0..3 -> rows tm*8..tm*8+7
    const int tn    = lane & 7;               // 0..7
    const int mBase = blockIdx.x * BM_;

    // ---- fill As: transpose g_pool[mBase..mBase+31][0..799] -> As[k][m] ----
    // scalar-k partition: coalesced LDG.32, STS lane-stride 34 (2-way).
    {
        const float* __restrict__ src = g_pool + (size_t)mBase * D_;
        #pragma unroll 4
        for (int it = 0; it < 100; ++it) {
            int idx = it * 256 + tid;          // 0..25599
            int row = idx / D_;                // 0..31
            int k   = idx - row * D_;          // 0..799
            As[k * ASTR_ + row] = src[row * D_ + k];
        }
    }
    __syncthreads();

    ull acc[32];                 // [m(8)][np(4)] n-pairs, cols tn*8..tn*8+7
    ull accL[4];                 // col 64+tn, m-pairs
    #pragma unroll
    for (int i = 0; i < 32; ++i) acc[i] = 0ull;
    #pragma unroll
    for (int i = 0; i < 4; ++i) accL[i] = 0ull;

    const float4* __restrict__ W4 = reinterpret_cast<const float4*>(W);

    for (int c = 0; c < 2; ++c) {
        const int k0 = wrp * KSLICE_ + c * BKC_;

        // --- fill this warp's B chunk: W[k0..k0+50) x 72 (contiguous) ---
        {
            float4* dst = reinterpret_cast<float4*>(Bw);
            const float4* src = W4 + (size_t)k0 * (NLAB_ / 4);
            #pragma unroll 4
            for (int it = 0; it < 29; ++it) {      // 900 float4 total
                int idx = it * 32 + lane;
                if (idx < BW_FLOATS_ / 4) dst[idx] = src[idx];
            }
        }
        __syncwarp();

        // --- mainloop over 50 local k ---
        #pragma unroll 2
        for (int l = 0; l < BKC_; ++l) {
            const int kg = k0 + l;
            // A: 8 m-values as 4 packed pairs (aligned LDS.64)
            const ull* arow = reinterpret_cast<const ull*>(As + kg * ASTR_ + tm * 8);
            ull av0 = arow[0], av1 = arow[1], av2 = arow[2], av3 = arow[3];
            float a[8];
            unpack2(av0, a[0], a[1]); unpack2(av1, a[2], a[3]);
            unpack2(av2, a[4], a[5]); unpack2(av3, a[6], a[7]);

            // B: 4 n-pairs (cols tn*8..+7) + scalar last col (64+tn)
            const float* brow = Bw + l * NLAB_;
            const ull* bp = reinterpret_cast<const ull*>(brow + tn * 8);
            ull b0 = bp[0], b1 = bp[1], b2 = bp[2], b3 = bp[3];
            ull bl = splat2(brow[64 + tn]);

            #pragma unroll
            for (int m = 0; m < 8; ++m) {
                ull asp = splat2(a[m]);
                fma2(acc[m * 4 + 0], asp, b0);
                fma2(acc[m * 4 + 1], asp, b1);
                fma2(acc[m * 4 + 2], asp, b2);
                fma2(acc[m * 4 + 3], asp, b3);
            }
            fma2(accL[0], av0, bl);
            fma2(accL[1], av1, bl);
            fma2(accL[2], av2, bl);
            fma2(accL[3], av3, bl);
        }
        __syncwarp();
    }

    // ---- cross-slice reduction through smem (reuse As region) ----
    __syncthreads();   // all warps done reading As
    {
        float* red = smem + wrp * RED_FLOATS_;      // [32][72]
        #pragma unroll
        for (int m = 0; m < 8; ++m) {
            int row = tm * 8 + m;
            #pragma unroll
            for (int np = 0; np < 4; ++np) {
                float lo, hi;
                unpack2(acc[m * 4 + np], lo, hi);
                red[row * NLAB_ + tn * 8 + 2 * np]     = lo;
                red[row * NLAB_ + tn * 8 + 2 * np + 1] = hi;
            }
        }
        #pragma unroll
        for (int mp = 0; mp < 4; ++mp) {
            float lo, hi;
            unpack2(accL[mp], lo, hi);
            red[(tm * 8 + 2 * mp)     * NLAB_ + 64 + tn] = lo;
            red[(tm * 8 + 2 * mp + 1) * NLAB_ + 64 + tn] = hi;
        }
    }
    __syncthreads();

    // ---- final: 9 outputs/thread, sum 8 slices, add bias ----
    {
        const int m = tid >> 3;               // 0..31
        const int g = tid & 7;                // 0..7 -> cols g*9..g*9+8
        #pragma unroll
        for (int j = 0; j < 9; ++j) {
            int n = g * 9 + j;
            float s = 0.0f;
            #pragma unroll
            for (int sl = 0; sl < 8; ++sl)
                s += smem[sl * RED_FLOATS_ + m * NLAB_ + n];
            out[(size_t)(mBase + m) * NLAB_ + n] = s + bias[n];
        }
    }
}

// ---------------------------------------------------------------------------
// Launch wrapper
// Inputs (metadata order): batch_hs f32[64*1024*800], slot_begins i32[64*64],
// slot_lens i32[64*64], W_clf f32[800*72], b_clf f32[72].
// Output: f32[64*64*72].
// ---------------------------------------------------------------------------
extern "C" void kernel_launch(void* const* d_in, const int* in_sizes, int n_in,
                              void* d_out, int out_size)
{
    const float* hs     = (const float*)d_in[0];
    const int*   begins = (const int*)  d_in[1];
    const int*   lens   = (const int*)  d_in[2];
    const float* W      = (const float*)d_in[3];
    const float* bias   = (const float*)d_in[4];
    float*       out    = (float*)d_out;

    cudaFuncSetAttribute(gemm_kernel,
                         cudaFuncAttributeMaxDynamicSharedMemorySize,
                         SMEM_BYTES_);

    pool_kernel<<<NPOOL_, 256>>>(hs, begins, lens);
    gemm_kernel<<<NPOOL_ / BM_, 256, SMEM_BYTES_>>>(W, bias, out);
}

// round 6
// speedup vs baseline: 1.1160x; 1.1160x over previous
#include <cuda_runtime.h>
#include <cuda_bf16.h>
#include <cstdint>

// ---------------------------------------------------------------------------
// Problem constants
// ---------------------------------------------------------------------------
#define BS_    64
#define SEQ_   1024
#define D_     800
#define NSLOT_ 64
#define NLAB_  72
#define NPOOL_ (BS_ * NSLOT_)    // 4096
#define D4_    (D_ / 4)          // 200
#define MT_    128               // M rows per GEMM block
#define NKS_   4                 // K-slices

// Device scratch (allocation-free rule)
__device__ __nv_bfloat16 g_Ahi[NPOOL_ * D_];
__device__ __nv_bfloat16 g_Alo[NPOOL_ * D_];
__device__ __nv_bfloat16 g_Bhi[NLAB_ * D_];   // [72][800] (W transposed, K-major)
__device__ __nv_bfloat16 g_Blo[NLAB_ * D_];
__device__ float         g_part[NKS_][NPOOL_ * NLAB_];

__device__ __forceinline__ uint32_t pack_bf2(__nv_bfloat16 a, __nv_bfloat16 b) {
    __nv_bfloat162 t(a, b);
    return *reinterpret_cast<uint32_t*>(&t);
}

// mma.sync m16n8k16 row.col bf16 -> f32 (arch-agnostic PTX, sm_80+)
__device__ __forceinline__ void mma_bf16(float* c, const uint32_t* a,
                                         uint32_t b0, uint32_t b1) {
    asm volatile(
        "mma.sync.aligned.m16n8k16.row.col.f32.bf16.bf16.f32 "
        "{%0,%1,%2,%3}, {%4,%5,%6,%7}, {%8,%9}, {%0,%1,%2,%3};"
        : "+f"(c[0]), "+f"(c[1]), "+f"(c[2]), "+f"(c[3])
        : "r"(a[0]), "r"(a[1]), "r"(a[2]), "r"(a[3]), "r"(b0), "r"(b1));
}

// ---------------------------------------------------------------------------
// Kernel 1: ragged span mean pooling -> split-bf16 planes (hi, lo)
// ---------------------------------------------------------------------------
__global__ __launch_bounds__(256) void pool_kernel(
    const float* __restrict__ hs,
    const int*   __restrict__ begins,
    const int*   __restrict__ lens)
{
    const int slot  = blockIdx.x;
    const int b     = slot >> 6;
    const int begin = begins[slot];
    const int len   = lens[slot];
    const float inv = 1.0f / (float)(len + 1);

    const int t = threadIdx.x;
    if (t >= D4_) return;

    const float4* __restrict__ row =
        reinterpret_cast<const float4*>(hs) + (size_t)(b * SEQ_ + begin) * D4_;

    float4 acc = row[t];
    #pragma unroll 7
    for (int r = 1; r <= len; ++r) {
        float4 v = row[(size_t)r * D4_ + t];
        acc.x += v.x; acc.y += v.y; acc.z += v.z; acc.w += v.w;
    }
    float a0 = acc.x * inv, a1 = acc.y * inv, a2 = acc.z * inv, a3 = acc.w * inv;

    __nv_bfloat16 h0 = __float2bfloat16(a0), h1 = __float2bfloat16(a1);
    __nv_bfloat16 h2 = __float2bfloat16(a2), h3 = __float2bfloat16(a3);
    __nv_bfloat16 l0 = __float2bfloat16(a0 - __bfloat162float(h0));
    __nv_bfloat16 l1 = __float2bfloat16(a1 - __bfloat162float(h1));
    __nv_bfloat16 l2 = __float2bfloat16(a2 - __bfloat162float(h2));
    __nv_bfloat16 l3 = __float2bfloat16(a3 - __bfloat162float(h3));

    const size_t base = (size_t)slot * D_ + t * 4;
    uint2 hv = make_uint2(pack_bf2(h0, h1), pack_bf2(h2, h3));
    uint2 lv = make_uint2(pack_bf2(l0, l1), pack_bf2(l2, l3));
    *reinterpret_cast<uint2*>(g_Ahi + base) = hv;
    *reinterpret_cast<uint2*>(g_Alo + base) = lv;
}

// ---------------------------------------------------------------------------
// Kernel 2: W (800x72) -> transposed split-bf16 planes [72][800]
// ---------------------------------------------------------------------------
__global__ __launch_bounds__(256) void convw_kernel(const float* __restrict__ W)
{
    int idx = blockIdx.x * 256 + threadIdx.x;
    if (idx >= D_ * NLAB_) return;
    int k = idx / NLAB_;
    int n = idx - k * NLAB_;
    float w = W[idx];
    __nv_bfloat16 h = __float2bfloat16(w);
    g_Bhi[n * D_ + k] = h;
    g_Blo[n * D_ + k] = __float2bfloat16(w - __bfloat162float(h));
}

// ---------------------------------------------------------------------------
// Kernel 3: split-bf16 HMMA GEMM (mma.sync m16n8k16).
// Grid = 32 m-tiles x 4 K-slices (208,208,192,192). Block stages all operands
// in smem (padded stride 432B -> conflict-free fragment loads), 8 warps =
// 4 m-groups (32 rows) x 2 n-groups (5/4 of 9 n-tiles); 3 MMAs per term-k16.
// Writes fp32 K-partials to g_part[ks].
// ---------------------------------------------------------------------------
#define STRB_    432                      // padded row stride in bytes (216 bf16)
#define OFF_AHI_ 0
#define OFF_ALO_ (MT_ * STRB_)            // 55296
#define OFF_BHI_ (2 * MT_ * STRB_)        // 110592
#define OFF_BLO_ (OFF_BHI_ + NLAB_ * STRB_)  // 141696
#define SMEM_MMA_ (OFF_BLO_ + NLAB_ * STRB_) // 172800 B

__global__ __launch_bounds__(256, 1) void mma_kernel()
{
    extern __shared__ char smem[];
    const int tid = threadIdx.x;

    const int mtile = blockIdx.x >> 2;
    const int ks    = blockIdx.x & 3;
    const int k0    = (ks < 2) ? ks * 208 : 416 + (ks - 2) * 192;
    const int klen  = (ks < 2) ? 208 : 192;
    const int nu2   = klen >> 2;          // uint2 (4 bf16) per row: 52 or 48
    const int steps = klen >> 4;          // 13 or 12

    // ---- stage A planes: 128 rows x klen bf16 each ----
    for (int u = tid; u < MT_ * 52; u += 256) {
        int r = u / 52, c = u - r * 52;
        if (c < nu2) {
            size_t goff = ((size_t)(mtile * MT_ + r) * D_ + k0 + c * 4);
            *(uint2*)(smem + OFF_AHI_ + r * STRB_ + c * 8) =
                *reinterpret_cast<const uint2*>(g_Ahi + goff);
            *(uint2*)(smem + OFF_ALO_ + r * STRB_ + c * 8) =
                *reinterpret_cast<const uint2*>(g_Alo + goff);
        }
    }
    // ---- stage B planes: 72 rows x klen bf16 each ----
    for (int u = tid; u < NLAB_ * 52; u += 256) {
        int r = u / 52, c = u - r * 52;
        if (c < nu2) {
            size_t goff = ((size_t)r * D_ + k0 + c * 4);
            *(uint2*)(smem + OFF_BHI_ + r * STRB_ + c * 8) =
                *reinterpret_cast<const uint2*>(g_Bhi + goff);
            *(uint2*)(smem + OFF_BLO_ + r * STRB_ + c * 8) =
                *reinterpret_cast<const uint2*>(g_Blo + goff);
        }
    }
    __syncthreads();

    const int wid  = tid >> 5;
    const int lane = tid & 31;
    const int g    = lane >> 2;           // fragment group 0..7
    const int t    = lane & 3;            // fragment thread 0..3
    const int mg   = wid >> 1;            // 0..3 -> rows mg*32..+31
    const int ng   = wid & 1;             // 0..1 -> n-tiles [0,5) / [5,9)
    const int j0   = ng * 5;
    const int jn   = ng ? 4 : 5;

    float acc[5][2][4];
    #pragma unroll
    for (int j = 0; j < 5; ++j)
        #pragma unroll
        for (int h = 0; h < 2; ++h)
            #pragma unroll
            for (int q = 0; q < 4; ++q) acc[j][h][q] = 0.0f;

    const char* Ahb = smem + OFF_AHI_ + (mg * 32 + g) * STRB_ + t * 4;
    const char* Alb = smem + OFF_ALO_ + (mg * 32 + g) * STRB_ + t * 4;
    const char* Bhb = smem + OFF_BHI_ + (j0 * 8 + g) * STRB_ + t * 4;
    const char* Blb = smem + OFF_BLO_ + (j0 * 8 + g) * STRB_ + t * 4;

    for (int s = 0; s < steps; ++s) {
        const int ko = s * 32;            // byte offset of this k16 chunk

        uint32_t ah[2][4], al[2][4];
        #pragma unroll
        for (int h = 0; h < 2; ++h) {
            const char* ph = Ahb + h * 16 * STRB_ + ko;
            ah[h][0] = *(const uint32_t*)(ph);
            ah[h][1] = *(const uint32_t*)(ph + 8 * STRB_);
            ah[h][2] = *(const uint32_t*)(ph + 16);
            ah[h][3] = *(const uint32_t*)(ph + 8 * STRB_ + 16);
            const char* pl = Alb + h * 16 * STRB_ + ko;
            al[h][0] = *(const uint32_t*)(pl);
            al[h][1] = *(const uint32_t*)(pl + 8 * STRB_);
            al[h][2] = *(const uint32_t*)(pl + 16);
            al[h][3] = *(const uint32_t*)(pl + 8 * STRB_ + 16);
        }

        #pragma unroll
        for (int j = 0; j < 5; ++j) {
            if (j < jn) {
                const char* bh = Bhb + j * 8 * STRB_ + ko;
                uint32_t bh0 = *(const uint32_t*)(bh);
                uint32_t bh1 = *(const uint32_t*)(bh + 16);
                const char* bl = Blb + j * 8 * STRB_ + ko;
                uint32_t bl0 = *(const uint32_t*)(bl);
                uint32_t bl1 = *(const uint32_t*)(bl + 16);
                #pragma unroll
                for (int h = 0; h < 2; ++h) {
                    mma_bf16(acc[j][h], ah[h], bh0, bh1);
                    mma_bf16(acc[j][h], ah[h], bl0, bl1);
                    mma_bf16(acc[j][h], al[h], bh0, bh1);
                }
            }
        }
    }

    // ---- epilogue: write K-partial ----
    float* dst = g_part[ks];
    #pragma unroll
    for (int j = 0; j < 5; ++j) {
        if (j < jn) {
            const int col = (j0 + j) * 8 + 2 * t;
            #pragma unroll
            for (int h = 0; h < 2; ++h) {
                const int row0 = mtile * MT_ + mg * 32 + h * 16 + g;
                *(float2*)(dst + (size_t)row0 * NLAB_ + col) =
                    make_float2(acc[j][h][0], acc[j][h][1]);
                *(float2*)(dst + (size_t)(row0 + 8) * NLAB_ + col) =
                    make_float2(acc[j][h][2], acc[j][h][3]);
            }
        }
    }
}

// ---------------------------------------------------------------------------
// Kernel 4: reduce the 4 K-partials + bias -> output
// ---------------------------------------------------------------------------
__global__ __launch_bounds__(256) void reduce_kernel(
    const float* __restrict__ bias,
    float*       __restrict__ out)
{
    int i = blockIdx.x * 256 + threadIdx.x;          // float4 index, 73728 total
    const float4* p0 = reinterpret_cast<const float4*>(g_part[0]);
    const float4* p1 = reinterpret_cast<const float4*>(g_part[1]);
    const float4* p2 = reinterpret_cast<const float4*>(g_part[2]);
    const float4* p3 = reinterpret_cast<const float4*>(g_part[3]);
    float4 a = p0[i], b = p1[i], c = p2[i], d = p3[i];
    int n = (i * 4) % NLAB_;
    float4 bv = *reinterpret_cast<const float4*>(bias + n);
    float4 o;
    o.x = a.x + b.x + c.x + d.x + bv.x;
    o.y = a.y + b.y + c.y + d.y + bv.y;
    o.z = a.z + b.z + c.z + d.z + bv.z;
    o.w = a.w + b.w + c.w + d.w + bv.w;
    reinterpret_cast<float4*>(out)[i] = o;
}

// ---------------------------------------------------------------------------
// Launch wrapper
// Inputs: batch_hs f32[64*1024*800], slot_begins i32[4096], slot_lens i32[4096],
// W_clf f32[800*72], b_clf f32[72]. Output: f32[4096*72].
// ---------------------------------------------------------------------------
extern "C" void kernel_launch(void* const* d_in, const int* in_sizes, int n_in,
                              void* d_out, int out_size)
{
    const float* hs     = (const float*)d_in[0];
    const int*   begins = (const int*)  d_in[1];
    const int*   lens   = (const int*)  d_in[2];
    const float* W      = (const float*)d_in[3];
    const float* bias   = (const float*)d_in[4];
    float*       out    = (float*)d_out;

    cudaFuncSetAttribute(mma_kernel,
                         cudaFuncAttributeMaxDynamicSharedMemorySize,
                         SMEM_MMA_);

    pool_kernel<<<NPOOL_, 256>>>(hs, begins, lens);
    convw_kernel<<<(D_ * NLAB_ + 255) / 256, 256>>>(W);
    mma_kernel<<<(NPOOL_ / MT_) * NKS_, 256, SMEM_MMA_>>>();
    reduce_kernel<<<(NPOOL_ * NLAB_ / 4) / 256, 256>>>(bias, out);
}

// round 7
// speedup vs baseline: 1.4517x; 1.3007x over previous
#include <cuda_runtime.h>
#include <cuda_bf16.h>
#include <cstdint>

// ---------------------------------------------------------------------------
// Problem constants
// ---------------------------------------------------------------------------
#define BS_    64
#define SEQ_   1024
#define D_     800
#define NSLOT_ 64
#define NLAB_  72
#define NPOOL_ (BS_ * NSLOT_)    // 4096
#define D4_    (D_ / 4)          // 200

// Device scratch (allocation-free rule)
__device__ __nv_bfloat16 g_Ahi[NPOOL_ * D_];
__device__ __nv_bfloat16 g_Alo[NPOOL_ * D_];
__device__ __nv_bfloat16 g_Bhi[NLAB_ * D_];   // [72][800] (W transposed, K-major)
__device__ __nv_bfloat16 g_Blo[NLAB_ * D_];

__device__ __forceinline__ uint32_t pack_bf2(__nv_bfloat16 a, __nv_bfloat16 b) {
    __nv_bfloat162 t(a, b);
    return *reinterpret_cast<uint32_t*>(&t);
}

// mma.sync m16n8k16 row.col bf16 -> f32 (arch-agnostic PTX, sm_80+)
__device__ __forceinline__ void mma_bf16(float* c, const uint32_t* a,
                                         uint32_t b0, uint32_t b1) {
    asm volatile(
        "mma.sync.aligned.m16n8k16.row.col.f32.bf16.bf16.f32 "
        "{%0,%1,%2,%3}, {%4,%5,%6,%7}, {%8,%9}, {%0,%1,%2,%3};"
        : "+f"(c[0]), "+f"(c[1]), "+f"(c[2]), "+f"(c[3])
        : "r"(a[0]), "r"(a[1]), "r"(a[2]), "r"(a[3]), "r"(b0), "r"(b1));
}

__device__ __forceinline__ uint32_t smem_u32(const void* p) {
    uint32_t a;
    asm("{ .reg .u64 t; cvta.to.shared.u64 t, %1; cvt.u32.u64 %0, t; }"
        : "=r"(a) : "l"(p));
    return a;
}
__device__ __forceinline__ void cp16(uint32_t dst, const void* src) {
    asm volatile("cp.async.cg.shared.global [%0], [%1], 16;"
                 :: "r"(dst), "l"(src));
}
__device__ __forceinline__ void cp_commit() {
    asm volatile("cp.async.commit_group;");
}
template <int N>
__device__ __forceinline__ void cp_wait() {
    asm volatile("cp.async.wait_group %0;" :: "n"(N));
}

// ---------------------------------------------------------------------------
// Kernel 1: ragged span mean pooling -> split-bf16 planes (hi, lo)
// ---------------------------------------------------------------------------
__global__ __launch_bounds__(256) void pool_kernel(
    const float* __restrict__ hs,
    const int*   __restrict__ begins,
    const int*   __restrict__ lens)
{
    const int slot  = blockIdx.x;
    const int b     = slot >> 6;
    const int begin = begins[slot];
    const int len   = lens[slot];
    const float inv = 1.0f / (float)(len + 1);

    const int t = threadIdx.x;
    if (t >= D4_) return;

    const float4* __restrict__ row =
        reinterpret_cast<const float4*>(hs) + (size_t)(b * SEQ_ + begin) * D4_;

    float4 acc = row[t];
    #pragma unroll 7
    for (int r = 1; r <= len; ++r) {
        float4 v = row[(size_t)r * D4_ + t];
        acc.x += v.x; acc.y += v.y; acc.z += v.z; acc.w += v.w;
    }
    float a0 = acc.x * inv, a1 = acc.y * inv, a2 = acc.z * inv, a3 = acc.w * inv;

    __nv_bfloat16 h0 = __float2bfloat16(a0), h1 = __float2bfloat16(a1);
    __nv_bfloat16 h2 = __float2bfloat16(a2), h3 = __float2bfloat16(a3);
    __nv_bfloat16 l0 = __float2bfloat16(a0 - __bfloat162float(h0));
    __nv_bfloat16 l1 = __float2bfloat16(a1 - __bfloat162float(h1));
    __nv_bfloat16 l2 = __float2bfloat16(a2 - __bfloat162float(h2));
    __nv_bfloat16 l3 = __float2bfloat16(a3 - __bfloat162float(h3));

    const size_t base = (size_t)slot * D_ + t * 4;
    uint2 hv = make_uint2(pack_bf2(h0, h1), pack_bf2(h2, h3));
    uint2 lv = make_uint2(pack_bf2(l0, l1), pack_bf2(l2, l3));
    *reinterpret_cast<uint2*>(g_Ahi + base) = hv;
    *reinterpret_cast<uint2*>(g_Alo + base) = lv;
}

// ---------------------------------------------------------------------------
// Kernel 2: W (800x72) -> transposed split-bf16 planes [72][800]
// ---------------------------------------------------------------------------
__global__ __launch_bounds__(256) void convw_kernel(const float* __restrict__ W)
{
    int idx = blockIdx.x * 256 + threadIdx.x;
    if (idx >= D_ * NLAB_) return;
    int k = idx / NLAB_;
    int n = idx - k * NLAB_;
    float w = W[idx];
    __nv_bfloat16 h = __float2bfloat16(w);
    g_Bhi[n * D_ + k] = h;
    g_Blo[n * D_ + k] = __float2bfloat16(w - __bfloat162float(h));
}

// ---------------------------------------------------------------------------
// Kernel 3: fused split-bf16 HMMA GEMM + bias (writes final output).
// Grid = 128 blocks x 32 rows, full K=800 in 5 double-buffered cp.async
// chunks of 160. 9 warps: warp w owns n8-tile w, both m16 halves.
// Per k16 step per warp: 16+4 LDS.32 fragment loads + 6 HMMA (3-term split).
// ---------------------------------------------------------------------------
#define MT_    32
#define BK_    160
#define NCH_   5                        // 800 / 160
#define STR_   336                      // padded row stride (320B data + 16)
#define OFF_AHI_ 0
#define OFF_ALO_ (MT_ * STR_)           // 10752
#define OFF_BHI_ (2 * MT_ * STR_)       // 21504
#define OFF_BLO_ (OFF_BHI_ + NLAB_ * STR_)   // 45696
#define STAGE_   (OFF_BLO_ + NLAB_ * STR_)   // 69888 per stage
#define SMEM_G_  (2 * STAGE_)                // 139776 B

__global__ __launch_bounds__(288, 1) void gemm_kernel(
    const float* __restrict__ bias,
    float*       __restrict__ out)
{
    extern __shared__ char smem[];
    const uint32_t sbase = smem_u32(smem);
    const int tid   = threadIdx.x;
    const int mtile = blockIdx.x;

    const char* gAh = (const char*)(g_Ahi + (size_t)mtile * MT_ * D_);
    const char* gAl = (const char*)(g_Alo + (size_t)mtile * MT_ * D_);
    const char* gBh = (const char*)g_Bhi;
    const char* gBl = (const char*)g_Blo;

    // issue_chunk: stage copies for K-chunk c into buffer (c % 2)
    auto issue_chunk = [&](int c) {
        const uint32_t st = sbase + (c & 1) * STAGE_;
        const int gk = c * (BK_ * 2);            // byte offset into K (bf16)
        // A planes: 2 x 32 rows x 20 x 16B
        for (int u = tid; u < 1280; u += 288) {
            int plane = u >> 9;                  // 0..1 wrong for 640 split
            plane = (u >= 640) ? 1 : 0;
            int rem = u - plane * 640;
            int r = rem / 20, i = rem - r * 20;
            const char* g = (plane ? gAl : gAh) + (size_t)r * (D_ * 2) + gk + i * 16;
            uint32_t d = st + (plane ? OFF_ALO_ : OFF_AHI_) + r * STR_ + i * 16;
            cp16(d, g);
        }
        // B planes: 2 x 72 rows x 20 x 16B
        for (int u = tid; u < 2880; u += 288) {
            int plane = (u >= 1440) ? 1 : 0;
            int rem = u - plane * 1440;
            int r = rem / 20, i = rem - r * 20;
            const char* g = (plane ? gBl : gBh) + (size_t)r * (D_ * 2) + gk + i * 16;
            uint32_t d = st + (plane ? OFF_BLO_ : OFF_BHI_) + r * STR_ + i * 16;
            cp16(d, g);
        }
        cp_commit();
    };

    const int lane = tid & 31;
    const int wid  = tid >> 5;            // 0..8 = n-tile
    const int g    = lane >> 2;
    const int t    = lane & 3;

    float acc[2][4];
    #pragma unroll
    for (int h = 0; h < 2; ++h)
        #pragma unroll
        for (int q = 0; q < 4; ++q) acc[h][q] = 0.0f;

    issue_chunk(0);

    for (int c = 0; c < NCH_; ++c) {
        if (c + 1 < NCH_) { issue_chunk(c + 1); cp_wait<1>(); }
        else              { cp_wait<0>(); }
        __syncthreads();

        const char* sb  = smem + (c & 1) * STAGE_;
        const char* Ahb = sb + OFF_AHI_ + g * STR_ + t * 4;
        const char* Alb = sb + OFF_ALO_ + g * STR_ + t * 4;
        const char* Bhb = sb + OFF_BHI_ + (wid * 8 + g) * STR_ + t * 4;
        const char* Blb = sb + OFF_BLO_ + (wid * 8 + g) * STR_ + t * 4;

        #pragma unroll
        for (int s = 0; s < BK_ / 16; ++s) {
            const int ko = s * 32;

            uint32_t bh0 = *(const uint32_t*)(Bhb + ko);
            uint32_t bh1 = *(const uint32_t*)(Bhb + ko + 16);
            uint32_t bl0 = *(const uint32_t*)(Blb + ko);
            uint32_t bl1 = *(const uint32_t*)(Blb + ko + 16);

            #pragma unroll
            for (int h = 0; h < 2; ++h) {
                const char* ph = Ahb + h * 16 * STR_ + ko;
                uint32_t ah[4];
                ah[0] = *(const uint32_t*)(ph);
                ah[1] = *(const uint32_t*)(ph + 8 * STR_);
                ah[2] = *(const uint32_t*)(ph + 16);
                ah[3] = *(const uint32_t*)(ph + 8 * STR_ + 16);
                const char* pl = Alb + h * 16 * STR_ + ko;
                uint32_t al[4];
                al[0] = *(const uint32_t*)(pl);
                al[1] = *(const uint32_t*)(pl + 8 * STR_);
                al[2] = *(const uint32_t*)(pl + 16);
                al[3] = *(const uint32_t*)(pl + 8 * STR_ + 16);

                mma_bf16(acc[h], ah, bh0, bh1);
                mma_bf16(acc[h], ah, bl0, bl1);
                mma_bf16(acc[h], al, bh0, bh1);
            }
        }
        __syncthreads();
    }

    // ---- epilogue: bias + final store ----
    const int col = wid * 8 + 2 * t;
    const float2 bv = *reinterpret_cast<const float2*>(bias + col);
    #pragma unroll
    for (int h = 0; h < 2; ++h) {
        const int row0 = mtile * MT_ + h * 16 + g;
        *(float2*)(out + (size_t)row0 * NLAB_ + col) =
            make_float2(acc[h][0] + bv.x, acc[h][1] + bv.y);
        *(float2*)(out + (size_t)(row0 + 8) * NLAB_ + col) =
            make_float2(acc[h][2] + bv.x, acc[h][3] + bv.y);
    }
}

// ---------------------------------------------------------------------------
// Launch wrapper
// Inputs: batch_hs f32[64*1024*800], slot_begins i32[4096], slot_lens i32[4096],
// W_clf f32[800*72], b_clf f32[72]. Output: f32[4096*72].
// ---------------------------------------------------------------------------
extern "C" void kernel_launch(void* const* d_in, const int* in_sizes, int n_in,
                              void* d_out, int out_size)
{
    const float* hs     = (const float*)d_in[0];
    const int*   begins = (const int*)  d_in[1];
    const int*   lens   = (const int*)  d_in[2];
    const float* W      = (const float*)d_in[3];
    const float* bias   = (const float*)d_in[4];
    float*       out    = (float*)d_out;

    cudaFuncSetAttribute(gemm_kernel,
                         cudaFuncAttributeMaxDynamicSharedMemorySize,
                         SMEM_G_);

    pool_kernel<<<NPOOL_, 256>>>(hs, begins, lens);
    convw_kernel<<<(D_ * NLAB_ + 255) / 256, 256>>>(W);
    gemm_kernel<<<NPOOL_ / MT_, 288, SMEM_G_>>>(bias, out);
}

// round 8
// speedup vs baseline: 1.5722x; 1.0830x over previous
#include <cuda_runtime.h>
#include <cuda_bf16.h>
#include <cstdint>

// ---------------------------------------------------------------------------
// Problem constants
// ---------------------------------------------------------------------------
#define BS_    64
#define SEQ_   1024
#define D_     800
#define NSLOT_ 64
#define NLAB_  72
#define NPOOL_ (BS_ * NSLOT_)    // 4096
#define D4_    (D_ / 4)          // 200

// Device scratch (allocation-free rule)
__device__ __nv_bfloat16 g_Ahi[NPOOL_ * D_];
__device__ __nv_bfloat16 g_Alo[NPOOL_ * D_];
__device__ __nv_bfloat16 g_Bhi[NLAB_ * D_];   // [72][800] (W transposed, K-major)
__device__ __nv_bfloat16 g_Blo[NLAB_ * D_];

__device__ __forceinline__ uint32_t pack_bf2(__nv_bfloat16 a, __nv_bfloat16 b) {
    __nv_bfloat162 t(a, b);
    return *reinterpret_cast<uint32_t*>(&t);
}

// mma.sync m16n8k16 row.col bf16 -> f32 (arch-agnostic PTX, sm_80+)
__device__ __forceinline__ void mma_bf16(float* c, const uint32_t* a,
                                         uint32_t b0, uint32_t b1) {
    asm volatile(
        "mma.sync.aligned.m16n8k16.row.col.f32.bf16.bf16.f32 "
        "{%0,%1,%2,%3}, {%4,%5,%6,%7}, {%8,%9}, {%0,%1,%2,%3};"
        : "+f"(c[0]), "+f"(c[1]), "+f"(c[2]), "+f"(c[3])
        : "r"(a[0]), "r"(a[1]), "r"(a[2]), "r"(a[3]), "r"(b0), "r"(b1));
}

__device__ __forceinline__ uint32_t smem_u32(const void* p) {
    uint32_t a;
    asm("{ .reg .u64 t; cvta.to.shared.u64 t, %1; cvt.u32.u64 %0, t; }"
        : "=r"(a) : "l"(p));
    return a;
}
__device__ __forceinline__ void cp16(uint32_t dst, const void* src) {
    asm volatile("cp.async.cg.shared.global [%0], [%1], 16;"
                 :: "r"(dst), "l"(src));
}
__device__ __forceinline__ void cp_commit() {
    asm volatile("cp.async.commit_group;");
}
template <int N>
__device__ __forceinline__ void cp_wait() {
    asm volatile("cp.async.wait_group %0;" :: "n"(N));
}

// ---------------------------------------------------------------------------
// Kernel 1: ragged span mean pooling -> split-bf16 planes.
// 4 slots per block: one int4 meta load, 4 independent accumulation streams
// per thread (up to ~18 predicated 16B loads in flight) for latency hiding.
// ---------------------------------------------------------------------------
__device__ __forceinline__ void acc_add(float4& a, float4 v) {
    a.x += v.x; a.y += v.y; a.z += v.z; a.w += v.w;
}
__device__ __forceinline__ void store_split(float4 a, float inv, size_t base) {
    float a0 = a.x * inv, a1 = a.y * inv, a2 = a.z * inv, a3 = a.w * inv;
    __nv_bfloat16 h0 = __float2bfloat16(a0), h1 = __float2bfloat16(a1);
    __nv_bfloat16 h2 = __float2bfloat16(a2), h3 = __float2bfloat16(a3);
    __nv_bfloat16 l0 = __float2bfloat16(a0 - __bfloat162float(h0));
    __nv_bfloat16 l1 = __float2bfloat16(a1 - __bfloat162float(h1));
    __nv_bfloat16 l2 = __float2bfloat16(a2 - __bfloat162float(h2));
    __nv_bfloat16 l3 = __float2bfloat16(a3 - __bfloat162float(h3));
    *reinterpret_cast<uint2*>(g_Ahi + base) =
        make_uint2(pack_bf2(h0, h1), pack_bf2(h2, h3));
    *reinterpret_cast<uint2*>(g_Alo + base) =
        make_uint2(pack_bf2(l0, l1), pack_bf2(l2, l3));
}

__global__ __launch_bounds__(256) void pool_kernel(
    const float* __restrict__ hs,
    const int*   __restrict__ begins,
    const int*   __restrict__ lens)
{
    const int t = threadIdx.x;
    if (t >= D4_) return;

    const int sbase = blockIdx.x * 4;          // 4 slots, same batch (4 | 64)
    const int b     = sbase >> 6;
    const int4 bg = *reinterpret_cast<const int4*>(begins + sbase);
    const int4 ln = *reinterpret_cast<const int4*>(lens + sbase);

    const float4* __restrict__ base =
        reinterpret_cast<const float4*>(hs) + (size_t)b * SEQ_ * D4_ + t;
    const float4* r0 = base + (size_t)bg.x * D4_;
    const float4* r1 = base + (size_t)bg.y * D4_;
    const float4* r2 = base + (size_t)bg.z * D4_;
    const float4* r3 = base + (size_t)bg.w * D4_;

    float4 a0 = r0[0], a1 = r1[0], a2 = r2[0], a3 = r3[0];
    #pragma unroll
    for (int r = 1; r < 8; ++r) {
        if (r <= ln.x) acc_add(a0, r0[(size_t)r * D4_]);
        if (r <= ln.y) acc_add(a1, r1[(size_t)r * D4_]);
        if (r <= ln.z) acc_add(a2, r2[(size_t)r * D4_]);
        if (r <= ln.w) acc_add(a3, r3[(size_t)r * D4_]);
    }

    const size_t ob = (size_t)sbase * D_ + t * 4;
    store_split(a0, 1.0f / (float)(ln.x + 1), ob);
    store_split(a1, 1.0f / (float)(ln.y + 1), ob + D_);
    store_split(a2, 1.0f / (float)(ln.z + 1), ob + 2 * D_);
    store_split(a3, 1.0f / (float)(ln.w + 1), ob + 3 * D_);
}

// ---------------------------------------------------------------------------
// Kernel 2: W (800x72) -> transposed split-bf16 planes [72][800]
// ---------------------------------------------------------------------------
__global__ __launch_bounds__(256) void convw_kernel(const float* __restrict__ W)
{
    int idx = blockIdx.x * 256 + threadIdx.x;
    if (idx >= D_ * NLAB_) return;
    int k = idx / NLAB_;
    int n = idx - k * NLAB_;
    float w = W[idx];
    __nv_bfloat16 h = __float2bfloat16(w);
    g_Bhi[n * D_ + k] = h;
    g_Blo[n * D_ + k] = __float2bfloat16(w - __bfloat162float(h));
}

// ---------------------------------------------------------------------------
// Kernel 3: fused split-bf16 HMMA GEMM + bias (writes final output).
// Grid = 128 blocks x 32 rows, full K=800 in 5 double-buffered cp.async
// chunks of 160. 6 warps = 2 m-groups (m16) x 3 n-groups (3 n8-tiles each).
// Per k16 step per warp: 8 A-LDS + 12 B-LDS + 9 HMMA (3-term split-bf16).
// ---------------------------------------------------------------------------
#define MT_    32
#define BK_    160
#define NCH_   5                        // 800 / 160
#define STR_   336                      // padded row stride (320B data + 16)
#define OFF_AHI_ 0
#define OFF_ALO_ (MT_ * STR_)           // 10752
#define OFF_BHI_ (2 * MT_ * STR_)       // 21504
#define OFF_BLO_ (OFF_BHI_ + NLAB_ * STR_)   // 45696
#define STAGE_   (OFF_BLO_ + NLAB_ * STR_)   // 69888 per stage
#define SMEM_G_  (2 * STAGE_)                // 139776 B
#define NT_      192                    // 6 warps

__global__ __launch_bounds__(NT_, 1) void gemm_kernel(
    const float* __restrict__ bias,
    float*       __restrict__ out)
{
    extern __shared__ char smem[];
    const uint32_t sbase = smem_u32(smem);
    const int tid   = threadIdx.x;
    const int mtile = blockIdx.x;

    const char* gAh = (const char*)(g_Ahi + (size_t)mtile * MT_ * D_);
    const char* gAl = (const char*)(g_Alo + (size_t)mtile * MT_ * D_);
    const char* gBh = (const char*)g_Bhi;
    const char* gBl = (const char*)g_Blo;

    auto issue_chunk = [&](int c) {
        const uint32_t st = sbase + (c & 1) * STAGE_;
        const int gk = c * (BK_ * 2);            // byte offset into K
        // A planes: 2 x 32 rows x 20 x 16B = 1280 units
        for (int u = tid; u < 1280; u += NT_) {
            int plane = (u >= 640) ? 1 : 0;
            int rem = u - plane * 640;
            int r = rem / 20, i = rem - r * 20;
            const char* g = (plane ? gAl : gAh) + (size_t)r * (D_ * 2) + gk + i * 16;
            cp16(st + (plane ? OFF_ALO_ : OFF_AHI_) + r * STR_ + i * 16, g);
        }
        // B planes: 2 x 72 rows x 20 x 16B = 2880 units
        for (int u = tid; u < 2880; u += NT_) {
            int plane = (u >= 1440) ? 1 : 0;
            int rem = u - plane * 1440;
            int r = rem / 20, i = rem - r * 20;
            const char* g = (plane ? gBl : gBh) + (size_t)r * (D_ * 2) + gk + i * 16;
            cp16(st + (plane ? OFF_BLO_ : OFF_BHI_) + r * STR_ + i * 16, g);
        }
        cp_commit();
    };

    const int lane = tid & 31;
    const int wid  = tid >> 5;            // 0..5
    const int mg   = wid & 1;             // m16 group
    const int ngrp = wid >> 1;            // 0..2 -> n8-tiles ngrp*3..+2
    const int g    = lane >> 2;
    const int t    = lane & 3;

    float acc[3][4];
    #pragma unroll
    for (int j = 0; j < 3; ++j)
        #pragma unroll
        for (int q = 0; q < 4; ++q) acc[j][q] = 0.0f;

    issue_chunk(0);

    for (int c = 0; c < NCH_; ++c) {
        if (c + 1 < NCH_) { issue_chunk(c + 1); cp_wait<1>(); }
        else              { cp_wait<0>(); }
        __syncthreads();

        const char* sb  = smem + (c & 1) * STAGE_;
        const char* Ahb = sb + OFF_AHI_ + (mg * 16 + g) * STR_ + t * 4;
        const char* Alb = sb + OFF_ALO_ + (mg * 16 + g) * STR_ + t * 4;
        const char* Bb0 = sb + OFF_BHI_ + (ngrp * 24 + g) * STR_ + t * 4;
        const char* Bl0 = sb + OFF_BLO_ + (ngrp * 24 + g) * STR_ + t * 4;

        #pragma unroll
        for (int s = 0; s < BK_ / 16; ++s) {
            const int ko = s * 32;

            uint32_t ah[4], al[4];
            ah[0] = *(const uint32_t*)(Ahb + ko);
            ah[1] = *(const uint32_t*)(Ahb + 8 * STR_ + ko);
            ah[2] = *(const uint32_t*)(Ahb + ko + 16);
            ah[3] = *(const uint32_t*)(Ahb + 8 * STR_ + ko + 16);
            al[0] = *(const uint32_t*)(Alb + ko);
            al[1] = *(const uint32_t*)(Alb + 8 * STR_ + ko);
            al[2] = *(const uint32_t*)(Alb + ko + 16);
            al[3] = *(const uint32_t*)(Alb + 8 * STR_ + ko + 16);

            #pragma unroll
            for (int j = 0; j < 3; ++j) {
                const char* bh = Bb0 + j * 8 * STR_ + ko;
                const char* bl = Bl0 + j * 8 * STR_ + ko;
                uint32_t bh0 = *(const uint32_t*)(bh);
                uint32_t bh1 = *(const uint32_t*)(bh + 16);
                uint32_t bl0 = *(const uint32_t*)(bl);
                uint32_t bl1 = *(const uint32_t*)(bl + 16);
                mma_bf16(acc[j], ah, bh0, bh1);
                mma_bf16(acc[j], ah, bl0, bl1);
                mma_bf16(acc[j], al, bh0, bh1);
            }
        }
        __syncthreads();
    }

    // ---- epilogue: bias + final store ----
    #pragma unroll
    for (int j = 0; j < 3; ++j) {
        const int col = (ngrp * 3 + j) * 8 + 2 * t;
        const float2 bv = *reinterpret_cast<const float2*>(bias + col);
        const int row0 = mtile * MT_ + mg * 16 + g;
        *(float2*)(out + (size_t)row0 * NLAB_ + col) =
            make_float2(acc[j][0] + bv.x, acc[j][1] + bv.y);
        *(float2*)(out + (size_t)(row0 + 8) * NLAB_ + col) =
            make_float2(acc[j][2] + bv.x, acc[j][3] + bv.y);
    }
}

// ---------------------------------------------------------------------------
// Launch wrapper
// Inputs: batch_hs f32[64*1024*800], slot_begins i32[4096], slot_lens i32[4096],
// W_clf f32[800*72], b_clf f32[72]. Output: f32[4096*72].
// ---------------------------------------------------------------------------
extern "C" void kernel_launch(void* const* d_in, const int* in_sizes, int n_in,
                              void* d_out, int out_size)
{
    const float* hs     = (const float*)d_in[0];
    const int*   begins = (const int*)  d_in[1];
    const int*   lens   = (const int*)  d_in[2];
    const float* W      = (const float*)d_in[3];
    const float* bias   = (const float*)d_in[4];
    float*       out    = (float*)d_out;

    cudaFuncSetAttribute(gemm_kernel,
                         cudaFuncAttributeMaxDynamicSharedMemorySize,
                         SMEM_G_);

    pool_kernel<<<NPOOL_ / 4, 256>>>(hs, begins, lens);
    convw_kernel<<<(D_ * NLAB_ + 255) / 256, 256>>>(W);
    gemm_kernel<<<NPOOL_ / MT_, NT_, SMEM_G_>>>(bias, out);
}